// round 10
// baseline (speedup 1.0000x reference)
#include <cuda_runtime.h>
#include <cstdint>
#include <math.h>

static constexpr int N_ROWS = 16384;
static constexpr int C_COLS = 1000;
static constexpr int ROWS_PER_BLOCK = 8;
static constexpr int THREADS = 256;
static constexpr int GRID = N_ROWS / ROWS_PER_BLOCK;   // 2048
static constexpr int N_PART = 1024;
static constexpr int HALF_BYTES = 4 * C_COLS * 4;      // 16000 B (4 rows)

__device__ float  g_alpha[C_COLS];
__device__ double g_part[N_PART];
__device__ int    g_done = 0;

// ---- TMA bulk copy + mbarrier helpers -------------------------------------
__device__ __forceinline__ void cp_bulk(unsigned int dst_smem, const void* src,
                                        unsigned int bytes, unsigned int mbar) {
    asm volatile(
        "cp.async.bulk.shared::cta.global.mbarrier::complete_tx::bytes "
        "[%0], [%1], %2, [%3];"
        :: "r"(dst_smem), "l"(src), "r"(bytes), "r"(mbar) : "memory");
}
__device__ __forceinline__ void mbar_init(unsigned int mbar, unsigned int cnt) {
    asm volatile("mbarrier.init.shared.b64 [%0], %1;" :: "r"(mbar), "r"(cnt) : "memory");
}
__device__ __forceinline__ void mbar_expect_tx(unsigned int mbar, unsigned int tx) {
    asm volatile("mbarrier.arrive.expect_tx.shared.b64 _, [%0], %1;"
                 :: "r"(mbar), "r"(tx) : "memory");
}
__device__ __forceinline__ void mbar_wait(unsigned int mbar, unsigned int parity) {
    unsigned int done;
    asm volatile(
        "{\n\t.reg .pred p;\n\t"
        "mbarrier.try_wait.parity.acquire.cta.shared::cta.b64 p, [%1], %2;\n\t"
        "selp.b32 %0, 1, 0, p;\n\t}"
        : "=r"(done) : "r"(mbar), "r"(parity) : "memory");
    if (!done) {
        asm volatile(
            "{\n\t.reg .pred P1;\n\t"
            "WAIT_LOOP_%=:\n\t"
            "mbarrier.try_wait.parity.acquire.cta.shared::cta.b64 P1, [%0], %1, 0x989680;\n\t"
            "@P1 bra.uni WAIT_DONE_%=;\n\t"
            "bra.uni WAIT_LOOP_%=;\n\t"
            "WAIT_DONE_%=:\n\t}"
            :: "r"(mbar), "r"(parity) : "memory");
    }
}

// ---------------------------------------------------------------------------
// Kernel 1: one block builds label histogram -> alpha[] table; zeros partials.
// ---------------------------------------------------------------------------
__global__ __launch_bounds__(1024)
void alpha_kernel(const int* __restrict__ label) {
    __shared__ int sh_counts[C_COLS];

    for (int i = threadIdx.x; i < C_COLS; i += 1024) sh_counts[i] = 0;
    if (threadIdx.x < N_PART) g_part[threadIdx.x] = 0.0;
    if (threadIdx.x == 0) g_done = 0;
    __syncthreads();

    const int4* lp = reinterpret_cast<const int4*>(label);
    for (int i = threadIdx.x; i < N_ROWS / 4; i += 1024) {
        int4 l4 = lp[i];
        if (l4.x >= 0 && l4.x < C_COLS) atomicAdd(&sh_counts[l4.x], 1);
        if (l4.y >= 0 && l4.y < C_COLS) atomicAdd(&sh_counts[l4.y], 1);
        if (l4.z >= 0 && l4.z < C_COLS) atomicAdd(&sh_counts[l4.z], 1);
        if (l4.w >= 0 && l4.w < C_COLS) atomicAdd(&sh_counts[l4.w], 1);
    }
    __syncthreads();

    for (int c = threadIdx.x; c < C_COLS; c += 1024) {
        float ni = (float)sh_counts[c];
        float r  = ni * (1.0f / (float)N_ROWS);
        g_alpha[c] = (ni > 0.0f) ? (__expf(r - 1.0f) / r) : 0.0f;
    }
}

// ---------------------------------------------------------------------------
// Kernel 2: 8 contiguous rows per block fetched by TWO TMA bulk copies
// (16000 B each) into smem; compute half 0 while half 1 streams.
// ---------------------------------------------------------------------------
__global__ __launch_bounds__(THREADS)
void row_kernel(const float* __restrict__ feature,
                const int* __restrict__ label,
                float* __restrict__ out) {
    const int tid  = threadIdx.x;
    const int lane = tid & 31;
    const int wid  = tid >> 5;
    const int row0 = blockIdx.x * ROWS_PER_BLOCK;

    __shared__ __align__(16) float sh_row[ROWS_PER_BLOCK * C_COLS]; // 32 KB
    __shared__ __align__(8) unsigned long long sh_bar[2];
    __shared__ float  sh_ws[THREADS / 32][ROWS_PER_BLOCK];
    __shared__ int    sh_lab[ROWS_PER_BLOCK];
    __shared__ int    sh_last;
    __shared__ double sh_dwarp[THREADS / 32];

    const unsigned int smem_row = (unsigned int)__cvta_generic_to_shared(sh_row);
    const unsigned int barA = (unsigned int)__cvta_generic_to_shared(&sh_bar[0]);
    const unsigned int barB = (unsigned int)__cvta_generic_to_shared(&sh_bar[1]);

    if (tid == 0) { mbar_init(barA, 1); mbar_init(barB, 1); }
    if (tid < ROWS_PER_BLOCK) {
        int l = label[row0 + tid];
        if (l < 0) l = 0;
        if (l >= C_COLS) l = C_COLS - 1;
        sh_lab[tid] = l;
    }
    __syncthreads();   // mbarriers initialized before any copy can complete

    if (tid == 0) {
        const float* g0 = feature + (size_t)row0 * C_COLS;
        mbar_expect_tx(barA, HALF_BYTES);
        cp_bulk(smem_row, g0, HALF_BYTES, barA);
        mbar_expect_tx(barB, HALF_BYTES);
        cp_bulk(smem_row + HALF_BYTES, g0 + 4 * C_COLS, HALF_BYTES, barB);
    }

    const bool active = tid < C_COLS / 4;   // 250 float4 lanes per row
    float s[ROWS_PER_BLOCK];
    #pragma unroll
    for (int r = 0; r < ROWS_PER_BLOCK; r++) s[r] = 0.0f;

    mbar_wait(barA, 0);
    if (active) {
        #pragma unroll
        for (int r = 0; r < 4; r++) {
            float4 v = *reinterpret_cast<const float4*>(&sh_row[r * C_COLS + tid * 4]);
            s[r] = __expf(v.x) + __expf(v.y) + __expf(v.z) + __expf(v.w);
        }
    }

    mbar_wait(barB, 0);
    if (active) {
        #pragma unroll
        for (int r = 4; r < 8; r++) {
            float4 v = *reinterpret_cast<const float4*>(&sh_row[r * C_COLS + tid * 4]);
            s[r] = __expf(v.x) + __expf(v.y) + __expf(v.z) + __expf(v.w);
        }
    }

    // Warp-reduce each row sum, stash per-warp results.
    #pragma unroll
    for (int r = 0; r < ROWS_PER_BLOCK; r++) {
        float x = s[r];
        #pragma unroll
        for (int o = 16; o > 0; o >>= 1)
            x += __shfl_xor_sync(0xFFFFFFFFu, x, o);
        if (lane == 0) sh_ws[wid][r] = x;
    }
    __syncthreads();

    // Threads 0-7: finish row tid, one spread double atomic each.
    if (tid < ROWS_PER_BLOCK) {
        float S = 0.0f;
        #pragma unroll
        for (int w = 0; w < THREADS / 32; w++) S += sh_ws[w][tid];
        int   l    = sh_lab[tid];
        float xl   = sh_row[tid * C_COLS + l];
        float logp = xl - __logf(S);
        float p    = __expf(logp);
        float omp  = 1.0f - p;
        atomicAdd(&g_part[(row0 + tid) & (N_PART - 1)],
                  (double)(g_alpha[l] * omp * omp * logp));
    }
    __syncthreads();

    if (tid == 0) {
        __threadfence();
        int prev = atomicAdd(&g_done, 1);
        sh_last = (prev == (int)gridDim.x - 1) ? 1 : 0;
        if (sh_last) __threadfence();
    }
    __syncthreads();

    if (sh_last) {
        double acc = 0.0;
        #pragma unroll
        for (int k = 0; k < N_PART / THREADS; k++)
            acc += __ldcg(&g_part[tid + k * THREADS]);
        #pragma unroll
        for (int o = 16; o > 0; o >>= 1)
            acc += __shfl_xor_sync(0xFFFFFFFFu, acc, o);
        if (lane == 0) sh_dwarp[wid] = acc;
        __syncthreads();
        if (tid == 0) {
            double tot = 0.0;
            #pragma unroll
            for (int w = 0; w < THREADS / 32; w++) tot += sh_dwarp[w];
            out[0] = (float)(-tot / (double)N_ROWS);
            g_done = 0;    // replay-safe reset
        }
    }
}

extern "C" void kernel_launch(void* const* d_in, const int* in_sizes, int n_in,
                              void* d_out, int out_size) {
    const float* feature = (const float*)d_in[0];
    const int*   label   = (const int*)d_in[1];
    float*       out     = (float*)d_out;

    alpha_kernel<<<1, 1024>>>(label);
    row_kernel<<<GRID, THREADS>>>(feature, label, out);
}

// round 11
// speedup vs baseline: 1.1385x; 1.1385x over previous
#include <cuda_runtime.h>
#include <cstdint>
#include <math.h>

static constexpr int N_ROWS = 16384;
static constexpr int C_COLS = 1000;
static constexpr int C_VEC  = C_COLS / 4;          // 250 float4 per row
static constexpr int ROWS_PER_BLOCK = 16;          // 8 LDG + 8 TMA
static constexpr int THREADS = 256;
static constexpr int GRID = N_ROWS / ROWS_PER_BLOCK;   // 1024
static constexpr int N_PART = 1024;
static constexpr int HALF_BYTES = 4 * C_COLS * 4;      // 16000 B (4 rows)

__device__ float  g_alpha[C_COLS];
__device__ double g_part[N_PART];
__device__ int    g_done = 0;

// ---- TMA bulk copy + mbarrier helpers -------------------------------------
__device__ __forceinline__ void cp_bulk(unsigned int dst_smem, const void* src,
                                        unsigned int bytes, unsigned int mbar) {
    asm volatile(
        "cp.async.bulk.shared::cta.global.mbarrier::complete_tx::bytes "
        "[%0], [%1], %2, [%3];"
        :: "r"(dst_smem), "l"(src), "r"(bytes), "r"(mbar) : "memory");
}
__device__ __forceinline__ void mbar_init(unsigned int mbar, unsigned int cnt) {
    asm volatile("mbarrier.init.shared.b64 [%0], %1;" :: "r"(mbar), "r"(cnt) : "memory");
}
__device__ __forceinline__ void mbar_expect_tx(unsigned int mbar, unsigned int tx) {
    asm volatile("mbarrier.arrive.expect_tx.shared.b64 _, [%0], %1;"
                 :: "r"(mbar), "r"(tx) : "memory");
}
__device__ __forceinline__ void mbar_wait(unsigned int mbar, unsigned int parity) {
    unsigned int done;
    asm volatile(
        "{\n\t.reg .pred p;\n\t"
        "mbarrier.try_wait.parity.acquire.cta.shared::cta.b64 p, [%1], %2;\n\t"
        "selp.b32 %0, 1, 0, p;\n\t}"
        : "=r"(done) : "r"(mbar), "r"(parity) : "memory");
    if (!done) {
        asm volatile(
            "{\n\t.reg .pred P1;\n\t"
            "WAIT_LOOP_%=:\n\t"
            "mbarrier.try_wait.parity.acquire.cta.shared::cta.b64 P1, [%0], %1, 0x989680;\n\t"
            "@P1 bra.uni WAIT_DONE_%=;\n\t"
            "bra.uni WAIT_LOOP_%=;\n\t"
            "WAIT_DONE_%=:\n\t}"
            :: "r"(mbar), "r"(parity) : "memory");
    }
}

// ---------------------------------------------------------------------------
// Kernel 1: one block builds label histogram -> alpha[] table; zeros partials.
// ---------------------------------------------------------------------------
__global__ __launch_bounds__(1024)
void alpha_kernel(const int* __restrict__ label) {
    __shared__ int sh_counts[C_COLS];

    for (int i = threadIdx.x; i < C_COLS; i += 1024) sh_counts[i] = 0;
    if (threadIdx.x < N_PART) g_part[threadIdx.x] = 0.0;
    if (threadIdx.x == 0) g_done = 0;
    __syncthreads();

    const int4* lp = reinterpret_cast<const int4*>(label);
    for (int i = threadIdx.x; i < N_ROWS / 4; i += 1024) {
        int4 l4 = lp[i];
        if (l4.x >= 0 && l4.x < C_COLS) atomicAdd(&sh_counts[l4.x], 1);
        if (l4.y >= 0 && l4.y < C_COLS) atomicAdd(&sh_counts[l4.y], 1);
        if (l4.z >= 0 && l4.z < C_COLS) atomicAdd(&sh_counts[l4.z], 1);
        if (l4.w >= 0 && l4.w < C_COLS) atomicAdd(&sh_counts[l4.w], 1);
    }
    __syncthreads();

    for (int c = threadIdx.x; c < C_COLS; c += 1024) {
        float ni = (float)sh_counts[c];
        float r  = ni * (1.0f / (float)N_ROWS);
        g_alpha[c] = (ni > 0.0f) ? (__expf(r - 1.0f) / r) : 0.0f;
    }
}

// ---------------------------------------------------------------------------
// Kernel 2: 16 rows/block. Rows 0-7: one per warp via direct LDG streaming
// (LSU path). Rows 8-15: staged by two cp.async.bulk copies (TMA path) that
// stream concurrently with the LDG compute; each warp then reduces one smem
// row. Both memory engines run in parallel.
// ---------------------------------------------------------------------------
__global__ __launch_bounds__(THREADS)
void row_kernel(const float* __restrict__ feature,
                const int* __restrict__ label,
                float* __restrict__ out) {
    const int tid  = threadIdx.x;
    const int lane = tid & 31;
    const int wid  = tid >> 5;
    const int row0 = blockIdx.x * ROWS_PER_BLOCK;

    __shared__ __align__(16) float sh_row[8 * C_COLS];   // 32 KB (TMA rows)
    __shared__ __align__(8) unsigned long long sh_bar[2];
    __shared__ int    sh_lab[ROWS_PER_BLOCK];
    __shared__ int    sh_last;
    __shared__ double sh_dwarp[THREADS / 32];

    const unsigned int smem_row = (unsigned int)__cvta_generic_to_shared(sh_row);
    const unsigned int barA = (unsigned int)__cvta_generic_to_shared(&sh_bar[0]);
    const unsigned int barB = (unsigned int)__cvta_generic_to_shared(&sh_bar[1]);

    if (tid == 0) { mbar_init(barA, 1); mbar_init(barB, 1); }
    if (tid < ROWS_PER_BLOCK) {
        int l = label[row0 + tid];
        if (l < 0) l = 0;
        if (l >= C_COLS) l = C_COLS - 1;
        sh_lab[tid] = l;
    }
    __syncthreads();   // bars + labels visible before copies can complete

    // Kick off the TMA path for rows 8-15 (2 x 16000 B, contiguous in GMEM).
    if (tid == 0) {
        const float* g8 = feature + (size_t)(row0 + 8) * C_COLS;
        mbar_expect_tx(barA, HALF_BYTES);
        cp_bulk(smem_row, g8, HALF_BYTES, barA);
        mbar_expect_tx(barB, HALF_BYTES);
        cp_bulk(smem_row + HALF_BYTES, g8 + 4 * C_COLS, HALF_BYTES, barB);
    }

    // ---------------- LSU path: warp w owns row row0+w ----------------------
    {
        const int rowL = row0 + wid;
        float xl = 0.0f, al = 0.0f;
        if (lane == 0) {
            int l = sh_lab[wid];
            xl = __ldg(&feature[(size_t)rowL * C_COLS + l]);
            al = g_alpha[l];
        }

        const float4* rp =
            reinterpret_cast<const float4*>(feature + (size_t)rowL * C_COLS);
        float s = 0.0f;
        #pragma unroll
        for (int k = 0; k < 8; k++) {
            int idx = lane + k * 32;
            if (idx < C_VEC) {
                float4 v = rp[idx];
                s += __expf(v.x) + __expf(v.y) + __expf(v.z) + __expf(v.w);
            }
        }
        #pragma unroll
        for (int o = 16; o > 0; o >>= 1)
            s += __shfl_xor_sync(0xFFFFFFFFu, s, o);

        if (lane == 0) {
            float logp = xl - __logf(s);
            float p    = __expf(logp);
            float omp  = 1.0f - p;
            atomicAdd(&g_part[rowL & (N_PART - 1)],
                      (double)(al * omp * omp * logp));
        }
    }

    // ---------------- TMA path: warp w reduces smem row w -------------------
    {
        if (wid < 4) mbar_wait(barA, 0);
        else         mbar_wait(barB, 0);

        const float* sp = &sh_row[wid * C_COLS];
        float s = 0.0f;
        #pragma unroll
        for (int k = 0; k < 8; k++) {
            int idx = lane + k * 32;
            if (idx < C_VEC) {
                float4 v = *reinterpret_cast<const float4*>(sp + idx * 4);
                s += __expf(v.x) + __expf(v.y) + __expf(v.z) + __expf(v.w);
            }
        }
        #pragma unroll
        for (int o = 16; o > 0; o >>= 1)
            s += __shfl_xor_sync(0xFFFFFFFFu, s, o);

        if (lane == 0) {
            int   rowS = row0 + 8 + wid;
            int   l    = sh_lab[8 + wid];
            float xl   = sp[l];
            float al   = g_alpha[l];
            float logp = xl - __logf(s);
            float p    = __expf(logp);
            float omp  = 1.0f - p;
            atomicAdd(&g_part[rowS & (N_PART - 1)],
                      (double)(al * omp * omp * logp));
        }
    }

    // ---------------- Ticket + last-block final reduction -------------------
    __syncthreads();
    if (tid == 0) {
        __threadfence();
        int prev = atomicAdd(&g_done, 1);
        sh_last = (prev == (int)gridDim.x - 1) ? 1 : 0;
        if (sh_last) __threadfence();
    }
    __syncthreads();

    if (sh_last) {
        double acc = 0.0;
        #pragma unroll
        for (int k = 0; k < N_PART / THREADS; k++)
            acc += __ldcg(&g_part[tid + k * THREADS]);
        #pragma unroll
        for (int o = 16; o > 0; o >>= 1)
            acc += __shfl_xor_sync(0xFFFFFFFFu, acc, o);
        if (lane == 0) sh_dwarp[wid] = acc;
        __syncthreads();
        if (tid == 0) {
            double tot = 0.0;
            #pragma unroll
            for (int w = 0; w < THREADS / 32; w++) tot += sh_dwarp[w];
            out[0] = (float)(-tot / (double)N_ROWS);
            g_done = 0;    // replay-safe reset
        }
    }
}

extern "C" void kernel_launch(void* const* d_in, const int* in_sizes, int n_in,
                              void* d_out, int out_size) {
    const float* feature = (const float*)d_in[0];
    const int*   label   = (const int*)d_in[1];
    float*       out     = (float*)d_out;

    alpha_kernel<<<1, 1024>>>(label);
    row_kernel<<<GRID, THREADS>>>(feature, label, out);
}